// round 4
// baseline (speedup 1.0000x reference)
#include <cuda_runtime.h>
#include <math.h>

#define B 8
#define T 2048
#define H 1024
#define V 256
#define GRID 128
#define NTHR 256
#define UPC 8            // hidden units per CTA (1 per warp)

typedef unsigned long long ull;

#define PPC 16                   // positions per CTA in loss kernel
#define LOSS_GRID ((B*T)/PPC)    // 1024
#define LOSS_SMEM_FLOATS (PPC*1024 + PPC*256 + PPC)
#define LOSS_SMEM_BYTES  (LOSS_SMEM_FLOATS * 4)

// ---------------- device scratch (static; no allocation) ----------------
__device__ float    g_hs[B * T * H];        // hidden states, layout [t][b][j]
__device__ float    g_hbuf[2][B][H];        // double-buffered h for the recurrence
__device__ unsigned g_flags[GRID];          // per-CTA published-step counters
__device__ float    g_partials[LOSS_GRID];  // per-CTA NLL partial sums

// ---------------- packed f32x2 + sync helpers ----------------
__device__ __forceinline__ ull fma2(ull a, ull b, ull c) {
    ull d;
    asm("fma.rn.f32x2 %0, %1, %2, %3;" : "=l"(d) : "l"(a), "l"(b), "l"(c));
    return d;
}
__device__ __forceinline__ float2 unpk(ull v) {
    float2 r;
    asm("mov.b64 {%0, %1}, %2;" : "=f"(r.x), "=f"(r.y) : "l"(v));
    return r;
}
__device__ __forceinline__ unsigned ld_acq(const unsigned* p) {
    unsigned v;
    asm volatile("ld.acquire.gpu.global.u32 %0, [%1];" : "=r"(v) : "l"(p));
    return v;
}
__device__ __forceinline__ void st_rel(unsigned* p, unsigned v) {
    asm volatile("st.release.gpu.global.u32 [%0], %1;" :: "l"(p), "r"(v) : "memory");
}
// fast exact-enough tanh via ex2-based expf
__device__ __forceinline__ float tanh_fast(float x) {
    return 2.0f / (1.0f + __expf(-2.0f * x)) - 1.0f;
}
__device__ __forceinline__ float sigmoid_fast(float x) {
    return 1.0f / (1.0f + __expf(-x));
}

// ---------------- reset: zero flags + h0 ----------------
__global__ void reset_kernel() {
    int tid = threadIdx.x;
    if (tid < GRID) g_flags[tid] = 0u;
    float* h0 = (float*)g_hbuf;        // buffer 0 = first B*H floats
    for (int i = tid; i < B * H; i += blockDim.x) h0[i] = 0.0f;
}

// ---------------- persistent LSTM kernel (weights in registers) ----------------
__global__ void __launch_bounds__(NTHR, 1)
lstm_kernel(const int* __restrict__ Xs,
            const float* __restrict__ W_ih,
            const float* __restrict__ W_hh,
            const float* __restrict__ b_ih,
            const float* __restrict__ b_hh)
{
    // h tile: [B][32 lanes][8 float4], XOR-swizzled on the low 3 f4-bits
    __shared__ float4 h4s[B * 256];         // 32 KB
    __shared__ float  scr[UPC][32];         // gate-scatter scratch, 1 KB

    const int tid  = threadIdx.x;
    const int wid  = tid >> 5;              // unit within CTA
    const int lane = tid & 31;              // K-chunk: [lane*32, lane*32+32)
    const int j0   = blockIdx.x * UPC;
    const int j    = j0 + wid;
    const int cta  = blockIdx.x;

    // staging geometry: this thread stages float4 column j4=tid for all B rows;
    // producer of those h columns is CTA (tid>>1)
    const unsigned* myflag = &g_flags[tid >> 1];
    const int l2 = tid >> 3;
    const int i2 = tid & 7;
    const int sts_idx = l2 * 8 + ((i2 + l2) & 7);

    // ---- load this thread's 128 weight floats into registers (once) ----
    ull w2[4][16];
    #pragma unroll
    for (int g = 0; g < 4; ++g) {
        const ulonglong2* src =
            (const ulonglong2*)&W_hh[(g * H + j) * H + lane * 32];
        #pragma unroll
        for (int i = 0; i < 8; ++i) {
            ulonglong2 tt = src[i];
            w2[g][2*i]   = tt.x;
            w2[g][2*i+1] = tt.y;
        }
    }
    float bias0 = b_ih[0*H + j] + b_hh[0*H + j];
    float bias1 = b_ih[1*H + j] + b_hh[1*H + j];
    float bias2 = b_ih[2*H + j] + b_hh[2*H + j];
    float bias3 = b_ih[3*H + j] + b_hh[3*H + j];

    float c_reg = 0.0f;                     // cell state for (b=lane, j), lanes 0..7

    for (int t = 0; t < T; ++t) {
        // ---- prefetch input contribution (independent of h_t) ----
        int   x   = 0;
        float wi0 = 0.f, wi1 = 0.f, wi2 = 0.f, wi3 = 0.f;
        if (lane < 8) {
            x   = __ldg(&Xs[lane * T + t]);
            wi0 = __ldg(&W_ih[(0*H + j) * V + x]);
            wi1 = __ldg(&W_ih[(1*H + j) * V + x]);
            wi2 = __ldg(&W_ih[(2*H + j) * V + x]);
            wi3 = __ldg(&W_ih[(3*H + j) * V + x]);
        }

        // ---- fine-grained wait: only for the producer of my staged columns ----
        if (t > 0) {
            while (ld_acq(myflag) < (unsigned)t) { }
        }
        // ---- stage h_t columns j4=tid for all B rows (swizzled) ----
        {
            const float4* hb = (const float4*)g_hbuf[t & 1];
            #pragma unroll
            for (int b2 = 0; b2 < B; ++b2) {
                float4 vv = __ldcg(hb + b2 * 256 + tid);
                h4s[b2 * 256 + sts_idx] = vv;
            }
        }
        __syncthreads();

        // ---- gate partials: 512 FFMA2 per thread ----
        float v[32];
        const ulonglong2* hbase = (const ulonglong2*)h4s + lane * 8;
        #pragma unroll
        for (int b = 0; b < B; ++b) {
            ull a0 = 0ull, a1 = 0ull, a2 = 0ull, a3 = 0ull;
            const ulonglong2* hrow = hbase + b * 256;
            #pragma unroll
            for (int i = 0; i < 8; ++i) {
                ulonglong2 hv = hrow[(i + lane) & 7];
                a0 = fma2(w2[0][2*i],   hv.x, a0);
                a1 = fma2(w2[1][2*i],   hv.x, a1);
                a2 = fma2(w2[2][2*i],   hv.x, a2);
                a3 = fma2(w2[3][2*i],   hv.x, a3);
                a0 = fma2(w2[0][2*i+1], hv.y, a0);
                a1 = fma2(w2[1][2*i+1], hv.y, a1);
                a2 = fma2(w2[2][2*i+1], hv.y, a2);
                a3 = fma2(w2[3][2*i+1], hv.y, a3);
            }
            float2 f0 = unpk(a0), f1 = unpk(a1), f2 = unpk(a2), f3 = unpk(a3);
            v[0*8 + b] = f0.x + f0.y;
            v[1*8 + b] = f1.x + f1.y;
            v[2*8 + b] = f2.x + f2.y;
            v[3*8 + b] = f3.x + f3.y;
        }

        // ---- multi-value butterfly: reduce 32 outputs across 32 lanes ----
        #pragma unroll
        for (int s = 0; s < 5; ++s) {
            const int m   = 1 << s;
            const int cnt = 16 >> s;
            const bool up = (lane & m) != 0;
            #pragma unroll
            for (int i = 0; i < cnt; ++i) {
                float send = up ? v[i] : v[i + cnt];
                float recv = __shfl_xor_sync(0xffffffffu, send, m);
                float keep = up ? v[i + cnt] : v[i];
                v[i] = keep + recv;
            }
        }
        // lane holds output o = bitrev5(lane): o = g*8 + b
        {
            int o = (int)(__brev((unsigned)lane) >> 27);
            scr[wid][o] = v[0];
        }
        __syncwarp();

        float hnew = 0.0f;
        if (lane < 8) {
            const int b = lane;
            float g0 = scr[wid][0*8 + b] + wi0 + bias0;
            float g1 = scr[wid][1*8 + b] + wi1 + bias1;
            float g2 = scr[wid][2*8 + b] + wi2 + bias2;
            float g3 = scr[wid][3*8 + b] + wi3 + bias3;
            float ig = sigmoid_fast(g0);
            float fg = sigmoid_fast(g1);
            float gg = tanh_fast(g2);
            float og = sigmoid_fast(g3);
            c_reg = fg * c_reg + ig * gg;
            hnew  = og * tanh_fast(c_reg);
            g_hbuf[(t + 1) & 1][b][j] = hnew;
        }
        __threadfence();
        __syncthreads();
        if (tid == 0) st_rel(&g_flags[cta], (unsigned)(t + 1));
        // off-critical-path archive store
        if (lane < 8) g_hs[(t * B + lane) * H + j] = hnew;
    }
}

// ---------------- loss kernel: logits + logsumexp + NLL partials ----------------
__global__ void __launch_bounds__(256, 1)
loss_kernel(const int* __restrict__ ys,
            const float* __restrict__ W1,
            const float* __restrict__ b1)
{
    extern __shared__ float sm[];
    float* h_sm     = sm;                       // [PPC][1024]
    float* logit_sm = sm + PPC * 1024;          // [PPC][256]
    float* red      = logit_sm + PPC * 256;     // [PPC]

    const int tid  = threadIdx.x;
    const int pos0 = blockIdx.x * PPC;          // pos = t*B + b

    for (int idx4 = tid; idx4 < PPC * 1024 / 4; idx4 += 256) {
        int idx = idx4 * 4;
        *(float4*)&h_sm[idx] = *(const float4*)&g_hs[pos0 * 1024 + idx];
    }
    __syncthreads();

    ull acc2[PPC];
    #pragma unroll
    for (int p = 0; p < PPC; ++p) acc2[p] = 0ull;

    const ulonglong2* wrow = (const ulonglong2*)&W1[tid * 1024];
    for (int k4 = 0; k4 < 256; ++k4) {
        ulonglong2 w = __ldg(wrow + k4);
        #pragma unroll
        for (int p = 0; p < PPC; ++p) {
            ulonglong2 hv = *(const ulonglong2*)&h_sm[p * 1024 + k4 * 4];
            acc2[p] = fma2(w.x, hv.x, acc2[p]);
            acc2[p] = fma2(w.y, hv.y, acc2[p]);
        }
    }
    float bv = b1[tid];
    #pragma unroll
    for (int p = 0; p < PPC; ++p) {
        float2 f = unpk(acc2[p]);
        logit_sm[p * 256 + tid] = f.x + f.y + bv;
    }
    __syncthreads();

    const int wid = tid >> 5, lane = tid & 31;
    #pragma unroll
    for (int pp = 0; pp < 2; ++pp) {
        int p = wid * 2 + pp;
        const float* L = &logit_sm[p * 256];
        float vv[8];
        #pragma unroll
        for (int i = 0; i < 8; ++i) vv[i] = L[lane + 32 * i];
        float m = vv[0];
        #pragma unroll
        for (int i = 1; i < 8; ++i) m = fmaxf(m, vv[i]);
        for (int off = 16; off; off >>= 1)
            m = fmaxf(m, __shfl_xor_sync(0xffffffffu, m, off));
        float s = 0.0f;
        #pragma unroll
        for (int i = 0; i < 8; ++i) s += expf(vv[i] - m);
        for (int off = 16; off; off >>= 1)
            s += __shfl_xor_sync(0xffffffffu, s, off);
        if (lane == 0) {
            int pos = pos0 + p;                  // pos = t*B + b
            int b   = pos & 7;
            int t   = pos >> 3;
            int y   = __ldg(&ys[b * T + t]);
            float lse = m + logf(s);
            red[p] = lse - L[y];
        }
    }
    __syncthreads();
    if (tid == 0) {
        float ssum = 0.0f;
        #pragma unroll
        for (int p = 0; p < PPC; ++p) ssum += red[p];
        g_partials[blockIdx.x] = ssum;
    }
}

// ---------------- final reduction -> mean NLL ----------------
__global__ void final_kernel(float* __restrict__ out) {
    __shared__ float red[256];
    int tid = threadIdx.x;
    float s = 0.0f;
    for (int i = tid; i < LOSS_GRID; i += 256) s += g_partials[i];
    red[tid] = s;
    __syncthreads();
    for (int off = 128; off; off >>= 1) {
        if (tid < off) red[tid] += red[tid + off];
        __syncthreads();
    }
    if (tid == 0) out[0] = red[0] / (float)(B * T);
}

// ---------------- launch ----------------
extern "C" void kernel_launch(void* const* d_in, const int* in_sizes, int n_in,
                              void* d_out, int out_size)
{
    const int*   Xs   = (const int*)d_in[0];
    const int*   ys   = (const int*)d_in[1];
    /* d_in[2] = predict (always 0 here) */
    const float* W_ih = (const float*)d_in[3];
    const float* W_hh = (const float*)d_in[4];
    const float* b_ih = (const float*)d_in[5];
    const float* b_hh = (const float*)d_in[6];
    const float* W1   = (const float*)d_in[7];
    const float* b1   = (const float*)d_in[8];
    float* out = (float*)d_out;

    cudaFuncSetAttribute(loss_kernel, cudaFuncAttributeMaxDynamicSharedMemorySize,
                         LOSS_SMEM_BYTES);

    reset_kernel<<<1, 256>>>();
    lstm_kernel<<<GRID, NTHR>>>(Xs, W_ih, W_hh, b_ih, b_hh);
    loss_kernel<<<LOSS_GRID, 256, LOSS_SMEM_BYTES>>>(ys, W1, b1);
    final_kernel<<<1, 256>>>(out);
    (void)in_sizes; (void)n_in; (void)out_size;
}

// round 5
// speedup vs baseline: 2.4028x; 2.4028x over previous
#include <cuda_runtime.h>
#include <math.h>

#define B 8
#define T 2048
#define H 1024
#define V 256
#define GRID 128
#define NTHR 256
#define UPC 8            // hidden units per CTA (1 per warp)

typedef unsigned long long ull;

#define PPC 16                   // positions per CTA in loss kernel
#define LOSS_GRID ((B*T)/PPC)    // 1024
#define LOSS_SMEM_FLOATS (PPC*1024 + PPC*256 + PPC)
#define LOSS_SMEM_BYTES  (LOSS_SMEM_FLOATS * 4)

// ---------------- device scratch (static; no allocation) ----------------
__device__ float    g_hs[B * T * H];        // hidden states, layout [t][b][j]
__device__ float    g_hbuf[2][B][H];        // double-buffered h for the recurrence
__device__ unsigned g_flags[GRID];          // per-CTA published-step counters
__device__ float    g_partials[LOSS_GRID];  // per-CTA NLL partial sums

// ---------------- packed f32x2 + sync helpers ----------------
__device__ __forceinline__ ull fma2(ull a, ull b, ull c) {
    ull d;
    asm("fma.rn.f32x2 %0, %1, %2, %3;" : "=l"(d) : "l"(a), "l"(b), "l"(c));
    return d;
}
__device__ __forceinline__ float2 unpk(ull v) {
    float2 r;
    asm("mov.b64 {%0, %1}, %2;" : "=f"(r.x), "=f"(r.y) : "l"(v));
    return r;
}
__device__ __forceinline__ unsigned ld_cgv(const unsigned* p) {
    unsigned v;
    asm volatile("ld.global.cg.u32 %0, [%1];" : "=r"(v) : "l"(p));
    return v;
}
__device__ __forceinline__ void st_rel(unsigned* p, unsigned v) {
    asm volatile("st.release.gpu.global.u32 [%0], %1;" :: "l"(p), "r"(v) : "memory");
}
__device__ __forceinline__ float tanh_fast(float x) {
    return 2.0f / (1.0f + __expf(-2.0f * x)) - 1.0f;
}
__device__ __forceinline__ float sigmoid_fast(float x) {
    return 1.0f / (1.0f + __expf(-x));
}

// ---------------- reset: zero flags + h0 ----------------
__global__ void reset_kernel() {
    int tid = threadIdx.x;
    if (tid < GRID) g_flags[tid] = 0u;
    float* h0 = (float*)g_hbuf;        // buffer 0 = first B*H floats
    for (int i = tid; i < B * H; i += blockDim.x) h0[i] = 0.0f;
}

// ---------------- persistent LSTM kernel (weights in registers) ----------------
__global__ void __launch_bounds__(NTHR, 1)
lstm_kernel(const int* __restrict__ Xs,
            const float* __restrict__ W_ih,
            const float* __restrict__ W_hh,
            const float* __restrict__ b_ih,
            const float* __restrict__ b_hh)
{
    // h tile: [B][32 lanes][8 float4], XOR-swizzled on the low 3 f4-bits
    __shared__ float4 h4s[B * 256];         // 32 KB
    __shared__ float  scr[UPC][32];         // gate-scatter scratch, 1 KB

    const int tid  = threadIdx.x;
    const int wid  = tid >> 5;              // unit within CTA
    const int lane = tid & 31;              // K-chunk: [lane*32, lane*32+32)
    const int j0   = blockIdx.x * UPC;
    const int j    = j0 + wid;
    const int cta  = blockIdx.x;

    // ---- load this thread's 128 weight floats into registers (once) ----
    ull w2[4][16];
    #pragma unroll
    for (int g = 0; g < 4; ++g) {
        const ulonglong2* src =
            (const ulonglong2*)&W_hh[(g * H + j) * H + lane * 32];
        #pragma unroll
        for (int i = 0; i < 8; ++i) {
            ulonglong2 tt = src[i];
            w2[g][2*i]   = tt.x;
            w2[g][2*i+1] = tt.y;
        }
    }
    float bias0 = b_ih[0*H + j] + b_hh[0*H + j];
    float bias1 = b_ih[1*H + j] + b_hh[1*H + j];
    float bias2 = b_ih[2*H + j] + b_hh[2*H + j];
    float bias3 = b_ih[3*H + j] + b_hh[3*H + j];

    float c_reg = 0.0f;                     // cell state for (b=lane, j), lanes 0..7

    for (int t = 0; t < T; ++t) {
        // ---- prefetch input contribution (independent of h_t) ----
        float wi0 = 0.f, wi1 = 0.f, wi2 = 0.f, wi3 = 0.f;
        if (lane < 8) {
            int x = __ldg(&Xs[lane * T + t]);
            wi0 = __ldg(&W_ih[(0*H + j) * V + x]);
            wi1 = __ldg(&W_ih[(1*H + j) * V + x]);
            wi2 = __ldg(&W_ih[(2*H + j) * V + x]);
            wi3 = __ldg(&W_ih[(3*H + j) * V + x]);
        }

        // ---- wait: warp 0 polls all 128 flags in parallel (4 per lane) ----
        if (t > 0) {
            if (wid == 0) {
                const unsigned tgt = (unsigned)t;
                bool d0 = false, d1 = false, d2 = false, d3 = false;
                while (true) {
                    if (!d0) d0 = ld_cgv(&g_flags[lane])      >= tgt;
                    if (!d1) d1 = ld_cgv(&g_flags[lane + 32]) >= tgt;
                    if (!d2) d2 = ld_cgv(&g_flags[lane + 64]) >= tgt;
                    if (!d3) d3 = ld_cgv(&g_flags[lane + 96]) >= tgt;
                    if (__all_sync(0xffffffffu, d0 && d1 && d2 && d3)) break;
                    __nanosleep(40);
                }
                asm volatile("fence.acq_rel.gpu;" ::: "memory");
            }
            __syncthreads();
        }

        // ---- stage h_t into swizzled SMEM (bypass L1) ----
        {
            const float4* hb = (const float4*)g_hbuf[t & 1];
            #pragma unroll
            for (int f = tid; f < B * 256; f += NTHR) {
                int b2 = f >> 8;
                int l2 = (f >> 3) & 31;
                int i2 = f & 7;
                float4 vv = __ldcg(hb + f);
                h4s[b2 * 256 + l2 * 8 + ((i2 + l2) & 7)] = vv;
            }
        }
        __syncthreads();

        // ---- gate partials: 512 FFMA2 per thread ----
        float v[32];
        const ulonglong2* hbase = (const ulonglong2*)h4s + lane * 8;
        #pragma unroll
        for (int b = 0; b < B; ++b) {
            ull a0 = 0ull, a1 = 0ull, a2 = 0ull, a3 = 0ull;
            const ulonglong2* hrow = hbase + b * 256;
            #pragma unroll
            for (int i = 0; i < 8; ++i) {
                ulonglong2 hv = hrow[(i + lane) & 7];
                a0 = fma2(w2[0][2*i],   hv.x, a0);
                a1 = fma2(w2[1][2*i],   hv.x, a1);
                a2 = fma2(w2[2][2*i],   hv.x, a2);
                a3 = fma2(w2[3][2*i],   hv.x, a3);
                a0 = fma2(w2[0][2*i+1], hv.y, a0);
                a1 = fma2(w2[1][2*i+1], hv.y, a1);
                a2 = fma2(w2[2][2*i+1], hv.y, a2);
                a3 = fma2(w2[3][2*i+1], hv.y, a3);
            }
            float2 f0 = unpk(a0), f1 = unpk(a1), f2 = unpk(a2), f3 = unpk(a3);
            v[0*8 + b] = f0.x + f0.y;
            v[1*8 + b] = f1.x + f1.y;
            v[2*8 + b] = f2.x + f2.y;
            v[3*8 + b] = f3.x + f3.y;
        }

        // ---- multi-value butterfly: reduce 32 outputs across 32 lanes ----
        #pragma unroll
        for (int s = 0; s < 5; ++s) {
            const int m   = 1 << s;
            const int cnt = 16 >> s;
            const bool up = (lane & m) != 0;
            #pragma unroll
            for (int i = 0; i < cnt; ++i) {
                float send = up ? v[i] : v[i + cnt];
                float recv = __shfl_xor_sync(0xffffffffu, send, m);
                float keep = up ? v[i + cnt] : v[i];
                v[i] = keep + recv;
            }
        }
        // lane holds output o = bitrev5(lane): o = g*8 + b
        {
            int o = (int)(__brev((unsigned)lane) >> 27);
            scr[wid][o] = v[0];
        }
        __syncwarp();

        float hnew = 0.0f;
        if (lane < 8) {
            const int b = lane;
            float g0 = scr[wid][0*8 + b] + wi0 + bias0;
            float g1 = scr[wid][1*8 + b] + wi1 + bias1;
            float g2 = scr[wid][2*8 + b] + wi2 + bias2;
            float g3 = scr[wid][3*8 + b] + wi3 + bias3;
            float ig = sigmoid_fast(g0);
            float fg = sigmoid_fast(g1);
            float gg = tanh_fast(g2);
            float og = sigmoid_fast(g3);
            c_reg = fg * c_reg + ig * gg;
            hnew  = og * tanh_fast(c_reg);
            g_hbuf[(t + 1) & 1][b][j] = hnew;
        }
        __syncthreads();
        if (tid == 0) st_rel(&g_flags[cta], (unsigned)(t + 1));
        // off-critical-path archive store
        if (lane < 8) g_hs[(t * B + lane) * H + j] = hnew;
    }
}

// ---------------- loss kernel: logits + logsumexp + NLL partials ----------------
__global__ void __launch_bounds__(256, 1)
loss_kernel(const int* __restrict__ ys,
            const float* __restrict__ W1,
            const float* __restrict__ b1)
{
    extern __shared__ float sm[];
    float* h_sm     = sm;                       // [PPC][1024]
    float* logit_sm = sm + PPC * 1024;          // [PPC][256]
    float* red      = logit_sm + PPC * 256;     // [PPC]

    const int tid  = threadIdx.x;
    const int pos0 = blockIdx.x * PPC;          // pos = t*B + b

    for (int idx4 = tid; idx4 < PPC * 1024 / 4; idx4 += 256) {
        int idx = idx4 * 4;
        *(float4*)&h_sm[idx] = *(const float4*)&g_hs[pos0 * 1024 + idx];
    }
    __syncthreads();

    ull acc2[PPC];
    #pragma unroll
    for (int p = 0; p < PPC; ++p) acc2[p] = 0ull;

    const ulonglong2* wrow = (const ulonglong2*)&W1[tid * 1024];
    for (int k4 = 0; k4 < 256; ++k4) {
        ulonglong2 w = __ldg(wrow + k4);
        #pragma unroll
        for (int p = 0; p < PPC; ++p) {
            ulonglong2 hv = *(const ulonglong2*)&h_sm[p * 1024 + k4 * 4];
            acc2[p] = fma2(w.x, hv.x, acc2[p]);
            acc2[p] = fma2(w.y, hv.y, acc2[p]);
        }
    }
    float bv = b1[tid];
    #pragma unroll
    for (int p = 0; p < PPC; ++p) {
        float2 f = unpk(acc2[p]);
        logit_sm[p * 256 + tid] = f.x + f.y + bv;
    }
    __syncthreads();

    const int wid = tid >> 5, lane = tid & 31;
    #pragma unroll
    for (int pp = 0; pp < 2; ++pp) {
        int p = wid * 2 + pp;
        const float* L = &logit_sm[p * 256];
        float vv[8];
        #pragma unroll
        for (int i = 0; i < 8; ++i) vv[i] = L[lane + 32 * i];
        float m = vv[0];
        #pragma unroll
        for (int i = 1; i < 8; ++i) m = fmaxf(m, vv[i]);
        for (int off = 16; off; off >>= 1)
            m = fmaxf(m, __shfl_xor_sync(0xffffffffu, m, off));
        float s = 0.0f;
        #pragma unroll
        for (int i = 0; i < 8; ++i) s += expf(vv[i] - m);
        for (int off = 16; off; off >>= 1)
            s += __shfl_xor_sync(0xffffffffu, s, off);
        if (lane == 0) {
            int pos = pos0 + p;                  // pos = t*B + b
            int b   = pos & 7;
            int t   = pos >> 3;
            int y   = __ldg(&ys[b * T + t]);
            float lse = m + logf(s);
            red[p] = lse - L[y];
        }
    }
    __syncthreads();
    if (tid == 0) {
        float ssum = 0.0f;
        #pragma unroll
        for (int p = 0; p < PPC; ++p) ssum += red[p];
        g_partials[blockIdx.x] = ssum;
    }
}

// ---------------- final reduction -> mean NLL ----------------
__global__ void final_kernel(float* __restrict__ out) {
    __shared__ float red[256];
    int tid = threadIdx.x;
    float s = 0.0f;
    for (int i = tid; i < LOSS_GRID; i += 256) s += g_partials[i];
    red[tid] = s;
    __syncthreads();
    for (int off = 128; off; off >>= 1) {
        if (tid < off) red[tid] += red[tid + off];
        __syncthreads();
    }
    if (tid == 0) out[0] = red[0] / (float)(B * T);
}

// ---------------- launch ----------------
extern "C" void kernel_launch(void* const* d_in, const int* in_sizes, int n_in,
                              void* d_out, int out_size)
{
    const int*   Xs   = (const int*)d_in[0];
    const int*   ys   = (const int*)d_in[1];
    /* d_in[2] = predict (always 0 here) */
    const float* W_ih = (const float*)d_in[3];
    const float* W_hh = (const float*)d_in[4];
    const float* b_ih = (const float*)d_in[5];
    const float* b_hh = (const float*)d_in[6];
    const float* W1   = (const float*)d_in[7];
    const float* b1   = (const float*)d_in[8];
    float* out = (float*)d_out;

    cudaFuncSetAttribute(loss_kernel, cudaFuncAttributeMaxDynamicSharedMemorySize,
                         LOSS_SMEM_BYTES);

    reset_kernel<<<1, 256>>>();
    lstm_kernel<<<GRID, NTHR>>>(Xs, W_ih, W_hh, b_ih, b_hh);
    loss_kernel<<<LOSS_GRID, 256, LOSS_SMEM_BYTES>>>(ys, W1, b1);
    final_kernel<<<1, 256>>>(out);
    (void)in_sizes; (void)n_in; (void)out_size;
}